// round 6
// baseline (speedup 1.0000x reference)
#include <cuda_runtime.h>
#include <cuda_fp16.h>
#include <mma.h>
#include <cstdint>
#include <math.h>

using namespace nvcuda;

// Problem constants
#define TSTEPS 512
#define BATCH  512
#define IDIM   128
#define HDIM   512
#define KACT   640   // reordered: cols [0,512)=h, [512,640)=inp

// Partitioning: 8 batch-groups x 16 CTAs = 128 CTAs (1 per SM, all resident)
// Each group is ONE hardware cluster of 16 CTAs.
#define NGROUPS 8
#define GCTAS   16
#define NCTA    (NGROUPS*GCTAS)
#define MB      64
#define HS      32
#define NTHREADS 512   // 16 warps: 4 warp-rows x 4 warp-cols

// SMEM padding / tiling
#define WPAD 648      // weight row stride (halfs)
#define FPAD 40       // Hloc / fc-weight row stride (halfs)
#define GPAD 132      // gates staging row stride (floats)
#define APAD 72       // A-stage row stride (halfs); 144B rows, 16B aligned
#define CHUNK 64      // K columns per staged chunk (per term)
#define NCHUNK 10
#define HCHUNK 8      // chunks [0,8) = h region, [8,10) = inp region

// SMEM layout (bytes):
//  Wsm  128*WPAD*2          = 165888
//  FCsm 128*FPAD*2          =  10240
//  R    max(gsm 64*GPAD*4=33792, Ast 2*2*64*APAD*2=36864) = 36864 (aliased)
//  Hloc 2*64*FPAD*2         =  10240
//  csm  64*32*4             =   8192
//  bsm  128*4               =    512
#define SMEM_BYTES (165888 + 10240 + 36864 + 10240 + 8192 + 512)   // 231936

// Global state
__device__ __align__(16) __half g_act[2][2][BATCH][KACT];   // [parity][term][row][col]
__device__ float g_fcpart[NGROUPS*GCTAS*MB*IDIM];

#define CLU_ARRIVE() asm volatile("barrier.cluster.arrive.aligned;" ::: "memory")
#define CLU_WAIT()   asm volatile("barrier.cluster.wait.aligned;" ::: "memory")

__device__ __forceinline__ uint4 ldcg4(const void* p) {
    return __ldcg(reinterpret_cast<const uint4*>(p));
}

// Overflow-safe fast sigmoid/tanh (EX2+RCP MUFU path, rel err ~2^-21)
__device__ __forceinline__ float fsigmoid(float z) {
    float e = __expf(-fabsf(z));
    float num = (z >= 0.f) ? 1.f : e;
    return __fdividef(num, 1.f + e);
}
__device__ __forceinline__ float ftanh_(float z) {
    float e = __expf(-2.f * fabsf(z));
    float r = __fdividef(1.f - e, 1.f + e);
    return (z >= 0.f) ? r : -r;
}

// Staged-chunk MMA over chunks [c_begin, c_end). Accumulates A(hi+lo) @ W^T.
// 16 warps: warp (wr,wc) owns output rows [wr*16,+16), cols [wc*32,+32).
// Staging: thread covers 16 halves (TWO uint4) of row lrow, term term_t:
//   term_t = tid>>8, lrow = (tid>>2)&63, lseg = tid&3  (halves [lseg*16, lseg*16+16))
// Coverage: 512 thr x 16 halves = 8192 halves = 2 terms x 64 rows x 64 cols. EXACT.
__device__ __forceinline__ void mma_chunks(
    wmma::fragment<wmma::accumulator, 16, 16, 16, float> (&acc)[2],
    const __half* __restrict__ gact_p,   // &g_act[p][0][0][0]; term stride = BATCH*KACT
    __half* __restrict__ Ast,            // [2 buf][2 term][64][APAD]
    const __half* __restrict__ Wsm,
    int row0, int wr, int wc, int term_t, int lrow, int lseg,
    int c_begin, int c_end)
{
    const __half* src = gact_p + (size_t)term_t * (BATCH*KACT)
                               + (size_t)(row0 + lrow) * KACT + lseg*16;
    __half* dst = Ast + (term_t*64 + lrow)*APAD + lseg*16;

    // stage chunk c_begin into buf 0 (16 halves = 2 x uint4)
    {
        uint4 v0 = ldcg4(src + c_begin*CHUNK);
        uint4 v1 = ldcg4(src + c_begin*CHUNK + 8);
        uint4* d = reinterpret_cast<uint4*>(dst);
        d[0] = v0; d[1] = v1;
    }
    __syncthreads();

    int buf = 0;
    for (int cc = c_begin; cc < c_end; cc++) {
        uint4 p0, p1;
        const bool hn = (cc + 1 < c_end);
        if (hn) {
            p0 = ldcg4(src + (cc+1)*CHUNK);
            p1 = ldcg4(src + (cc+1)*CHUNK + 8);
        }

        const __half* Ab = Ast + buf * (2 * 64 * APAD);
        const int kbase = cc * CHUNK;
        #pragma unroll
        for (int kt = 0; kt < 4; kt++) {
            wmma::fragment<wmma::matrix_b, 16, 16, 16, __half, wmma::col_major> bf[2];
            #pragma unroll
            for (int j = 0; j < 2; j++)
                wmma::load_matrix_sync(bf[j], Wsm + (wc*32 + j*16)*WPAD + kbase + kt*16, WPAD);
            #pragma unroll
            for (int term = 0; term < 2; term++) {
                wmma::fragment<wmma::matrix_a, 16, 16, 16, __half, wmma::row_major> af;
                wmma::load_matrix_sync(af, Ab + (term*64 + wr*16)*APAD + kt*16, APAD);
                #pragma unroll
                for (int j = 0; j < 2; j++)
                    wmma::mma_sync(acc[j], af, bf[j], acc[j]);
            }
        }
        if (hn) {
            buf ^= 1;
            uint4* d = reinterpret_cast<uint4*>(
                Ast + buf*(2*64*APAD) + (term_t*64 + lrow)*APAD + lseg*16);
            d[0] = p0; d[1] = p1;
        }
        __syncthreads();
    }
}

__global__ void __launch_bounds__(NTHREADS, 1) __cluster_dims__(GCTAS, 1, 1)
decoder_kernel(
    const float* __restrict__ x,    const float* __restrict__ h0,
    const float* __restrict__ c0,   const float* __restrict__ W_ih,
    const float* __restrict__ W_hh, const float* __restrict__ b_ih,
    const float* __restrict__ b_hh, const float* __restrict__ fc_W,
    const float* __restrict__ fc_b, float* __restrict__ out)
{
    extern __shared__ unsigned char smem_raw[];
    __half* Wsm  = (__half*)smem_raw;                            // [128][WPAD]
    __half* FCsm = Wsm + 128*WPAD;                               // [128][FPAD]
    __half* Ast  = FCsm + 128*FPAD;                              // R: [2][2][64][APAD]
    float*  gsm  = (float*)Ast;                                  // R: [64][GPAD] (aliased)
    __half* Hloc = (__half*)(smem_raw + 165888 + 10240 + 36864); // [2][64][FPAD]
    float*  csm  = (float*)(Hloc + 2*64*FPAD);                   // [64][32]
    float*  bsm  = csm + 64*32;                                  // [128]

    const int tid  = threadIdx.x;
    const int gid  = blockIdx.x / GCTAS;
    const int rk   = blockIdx.x % GCTAS;
    const int row0 = gid * MB;
    const int hs   = rk * HS;

    const int wid = tid >> 5;
    const int wr  = wid >> 2;        // 0..3 : 16 output rows each
    const int wc  = wid & 3;         // 0..3 : 32 output cols each
    const int term_t = tid >> 8;     // 0..1 : staged term
    const int lrow   = (tid >> 2) & 63;
    const int lseg   = tid & 3;

    // ---------------- init (once) ----------------
    for (int idx = tid; idx < 128*KACT; idx += NTHREADS) {
        int r = idx / KACT, k = idx - r*KACT;
        int q = r >> 5, j = r & 31;
        int grow = q*HDIM + hs + j;
        float v = (k < HDIM) ? W_hh[grow*HDIM + k] : W_ih[grow*IDIM + (k - HDIM)];
        Wsm[r*WPAD + k] = __float2half_rn(v);
    }
    for (int idx = tid; idx < 128*HS; idx += NTHREADS) {
        int n = idx / HS, k = idx - n*HS;
        FCsm[n*FPAD + k] = __float2half_rn(fc_W[n*HDIM + hs + k]);
    }
    for (int r = tid; r < 128; r += NTHREADS) {
        int q = r >> 5, j = r & 31;
        bsm[r] = b_ih[q*HDIM + hs + j] + b_hh[q*HDIM + hs + j];
    }
    for (int idx = tid; idx < MB*HS; idx += NTHREADS) {
        int m = idx >> 5, j = idx & 31;
        csm[m*HS + j] = c0[(row0+m)*HDIM + hs + j];
    }
    for (int idx = tid; idx < MB*HS; idx += NTHREADS) {
        int m = idx >> 5, j = idx & 31;
        float v = h0[(row0+m)*HDIM + hs + j];
        __half hi = __float2half_rn(v);
        __half lo = __float2half_rn(v - __half2float(hi));
        g_act[0][0][row0+m][hs+j] = hi;
        g_act[0][1][row0+m][hs+j] = lo;
    }
    for (int idx = tid; idx < MB*8; idx += NTHREADS) {
        int m = idx >> 3, ccol = rk*8 + (idx & 7);
        float v = x[(TSTEPS-1)*BATCH*IDIM + (row0+m)*IDIM + ccol];
        __half hi = __float2half_rn(v);
        __half lo = __float2half_rn(v - __half2float(hi));
        g_act[0][0][row0+m][HDIM+ccol] = hi;
        g_act[0][1][row0+m][HDIM+ccol] = lo;
    }

    CLU_ARRIVE();
    CLU_WAIT();     // seeds visible cluster-wide

    // ---------------- prologue: gates(0) ----------------
    {
        wmma::fragment<wmma::accumulator, 16, 16, 16, float> acc[2];
        wmma::fill_fragment(acc[0], 0.0f);
        wmma::fill_fragment(acc[1], 0.0f);
        mma_chunks(acc, &g_act[0][0][0][0], Ast, Wsm, row0, wr, wc,
                   term_t, lrow, lseg, 0, NCHUNK);
        #pragma unroll
        for (int j = 0; j < 2; j++)
            wmma::store_matrix_sync(&gsm[(wr*16)*GPAD + wc*32 + j*16],
                                    acc[j], GPAD, wmma::mem_row_major);
        __syncthreads();
    }

    // ---------------- 512 sequential steps ----------------
    for (int t = 0; t < TSTEPS; t++) {
        const int pn = (t + 1) & 1;
        const bool more = (t < TSTEPS - 1);

        // ===== pointwise LSTM: gsm -> h_new (global pn + Hloc) =====
        #pragma unroll
        for (int it = 0; it < (MB*HS)/NTHREADS; it++) {
            int idx = tid + it*NTHREADS;
            int m = idx >> 5, j = idx & 31;
            float zi = gsm[m*GPAD +      j] + bsm[     j];
            float zf = gsm[m*GPAD + 32 + j] + bsm[32 + j];
            float zg = gsm[m*GPAD + 64 + j] + bsm[64 + j];
            float zo = gsm[m*GPAD + 96 + j] + bsm[96 + j];
            float c  = csm[m*HS + j];
            float ig = fsigmoid(zi);
            float fg = fsigmoid(zf);
            float gg = ftanh_(zg);
            float og = fsigmoid(zo);
            float cn = fg*c + ig*gg;
            float hn = og * ftanh_(cn);
            csm[m*HS + j] = cn;
            __half hi = __float2half_rn(hn);
            __half lo = __float2half_rn(hn - __half2float(hi));
            g_act[pn][0][row0+m][hs+j] = hi;
            g_act[pn][1][row0+m][hs+j] = lo;
            Hloc[(0*64 + m)*FPAD + j] = hi;
            Hloc[(1*64 + m)*FPAD + j] = lo;
        }
        __syncthreads();   // Hloc ready; gsm dead

        // ===== fc partial: [64 x 128] = (h_hi+h_lo)[64x32] @ fc_W_slice^T =====
        {
            wmma::fragment<wmma::accumulator, 16, 16, 16, float> pacc[2];
            wmma::fill_fragment(pacc[0], 0.0f);
            wmma::fill_fragment(pacc[1], 0.0f);
            #pragma unroll
            for (int tt = 0; tt < 2; tt++) {
                #pragma unroll
                for (int kt = 0; kt < 2; kt++) {
                    wmma::fragment<wmma::matrix_b, 16, 16, 16, __half, wmma::col_major> bf[2];
                    #pragma unroll
                    for (int j = 0; j < 2; j++)
                        wmma::load_matrix_sync(bf[j], FCsm + (wc*32 + j*16)*FPAD + kt*16, FPAD);
                    wmma::fragment<wmma::matrix_a, 16, 16, 16, __half, wmma::row_major> af;
                    wmma::load_matrix_sync(af, Hloc + (tt*64 + wr*16)*FPAD + kt*16, FPAD);
                    #pragma unroll
                    for (int j = 0; j < 2; j++)
                        wmma::mma_sync(pacc[j], af, bf[j], pacc[j]);
                }
            }
            float* base = &g_fcpart[((gid*GCTAS + rk)*MB)*IDIM];
            #pragma unroll
            for (int j = 0; j < 2; j++)
                wmma::store_matrix_sync(base + (wr*16)*IDIM + wc*32 + j*16,
                                        pacc[j], IDIM, wmma::mem_row_major);
        }

        CLU_ARRIVE();                 // A: h_new + fc partials published
        CLU_WAIT();                   // (only exposed barrier; skew only)

        // ===== finalize fc cols [rk*8, rk*8+8): reduce, activate, feedback =====
        {
            int m = tid >> 3, n = rk*8 + (tid & 7);
            float z = fc_b[n];
            #pragma unroll
            for (int s = 0; s < GCTAS; s++)
                z += __ldcg(&g_fcpart[((gid*GCTAS + s)*MB + m)*IDIM + n]);
            float y = ftanh_(0.5f * z);   // == 2*sigmoid(z) - 1
            out[(TSTEPS-1-t)*BATCH*IDIM + (row0+m)*IDIM + n] = y;
            __half hi = __float2half_rn(y);
            __half lo = __float2half_rn(y - __half2float(hi));
            g_act[pn][0][row0+m][HDIM+n] = hi;
            g_act[pn][1][row0+m][HDIM+n] = lo;
        }

        CLU_ARRIVE();                 // B: inp(t+1) published

        if (more) {
            // ===== gates(t+1): part1 over h chunks (hides barrier B latency) =====
            wmma::fragment<wmma::accumulator, 16, 16, 16, float> acc[2];
            wmma::fill_fragment(acc[0], 0.0f);
            wmma::fill_fragment(acc[1], 0.0f);
            const __half* gp = &g_act[pn][0][0][0];
            mma_chunks(acc, gp, Ast, Wsm, row0, wr, wc, term_t, lrow, lseg, 0, HCHUNK);

            CLU_WAIT();               // B: should already be satisfied

            mma_chunks(acc, gp, Ast, Wsm, row0, wr, wc, term_t, lrow, lseg, HCHUNK, NCHUNK);

            #pragma unroll
            for (int j = 0; j < 2; j++)
                wmma::store_matrix_sync(&gsm[(wr*16)*GPAD + wc*32 + j*16],
                                        acc[j], GPAD, wmma::mem_row_major);
            __syncthreads();
        } else {
            CLU_WAIT();               // keep arrive/wait strictly paired
        }
    }
}

extern "C" void kernel_launch(void* const* d_in, const int* in_sizes, int n_in,
                              void* d_out, int out_size)
{
    const float* x    = (const float*)d_in[0];
    // d_in[1] = enc_hiddens : unused by the reference recursion
    const float* h0   = (const float*)d_in[2];
    const float* c0   = (const float*)d_in[3];
    const float* W_ih = (const float*)d_in[4];
    const float* W_hh = (const float*)d_in[5];
    const float* b_ih = (const float*)d_in[6];
    const float* b_hh = (const float*)d_in[7];
    const float* fc_W = (const float*)d_in[8];
    const float* fc_b = (const float*)d_in[9];
    float* out = (float*)d_out;

    cudaFuncSetAttribute(decoder_kernel, cudaFuncAttributeMaxDynamicSharedMemorySize, SMEM_BYTES);
    cudaFuncSetAttribute(decoder_kernel, cudaFuncAttributeNonPortableClusterSizeAllowed, 1);

    decoder_kernel<<<NCTA, NTHREADS, SMEM_BYTES>>>(x, h0, c0, W_ih, W_hh,
                                                   b_ih, b_hh, fc_W, fc_b, out);
}

// round 7
// speedup vs baseline: 1.2401x; 1.2401x over previous
#include <cuda_runtime.h>
#include <cuda_fp16.h>
#include <mma.h>
#include <cstdint>
#include <math.h>

using namespace nvcuda;

// Problem constants
#define TSTEPS 512
#define BATCH  512
#define IDIM   128
#define HDIM   512
#define KACT   640   // reordered: cols [0,512)=h, [512,640)=inp

// Partitioning: 8 batch-groups x 16 CTAs = 128 CTAs (1 per SM, one wave)
#define NGROUPS 8
#define GCTAS   16
#define NCTA    (NGROUPS*GCTAS)
#define MB      64
#define HS      32
#define NTHREADS 512   // 16 warps: 4 warp-rows x 4 warp-cols

// SMEM padding / tiling
#define WPAD 648      // weight row stride (halfs)
#define FPAD 40       // Hloc / fc-weight row stride (halfs)
#define GPAD 132      // gates staging row stride (floats)
#define APAD 72       // A-stage row stride (halfs); 144B rows, 16B aligned
#define CHUNK 64      // K columns per staged chunk (per term)
#define NCHUNK 10
#define HCHUNK 8      // chunks [0,8) = h region, [8,10) = inp region

// SMEM layout (bytes):
//  Wsm  128*WPAD*2          = 165888
//  FCsm 128*FPAD*2          =  10240
//  R    max(gsm 64*GPAD*4=33792, Ast 2*2*64*APAD*2=36864) = 36864 (aliased)
//  Hloc 2*64*FPAD*2         =  10240
//  csm  64*32*4             =   8192
//  bsm  128*4               =    512
#define SMEM_BYTES (165888 + 10240 + 36864 + 10240 + 8192 + 512)   // 231936

// Global state
__device__ __align__(16) __half g_act[2][2][BATCH][KACT];   // [parity][term][row][col]
__device__ float g_fcpart[NGROUPS*GCTAS*MB*IDIM];
__device__ unsigned g_bar[NGROUPS];                          // monotonic barrier counters

__device__ __forceinline__ void bar_arrive(int gid) {
    if (threadIdx.x == 0) {
        __threadfence();                 // release my global writes
        atomicAdd(&g_bar[gid], 1u);
    }
}
__device__ __forceinline__ void bar_wait(int gid, unsigned target) {
    if (threadIdx.x == 0) {
        while (*((volatile unsigned*)&g_bar[gid]) < target) { __nanosleep(20); }
        __threadfence();                 // acquire others' global writes
    }
    __syncthreads();
}

__device__ __forceinline__ uint4 ldcg4(const void* p) {
    return __ldcg(reinterpret_cast<const uint4*>(p));
}

// Overflow-safe fast sigmoid/tanh (EX2+RCP MUFU path, rel err ~2^-21)
__device__ __forceinline__ float fsigmoid(float z) {
    float e = __expf(-fabsf(z));
    float num = (z >= 0.f) ? 1.f : e;
    return __fdividef(num, 1.f + e);
}
__device__ __forceinline__ float ftanh_(float z) {
    float e = __expf(-2.f * fabsf(z));
    float r = __fdividef(1.f - e, 1.f + e);
    return (z >= 0.f) ? r : -r;
}

// Staged-chunk MMA over chunks [c_begin, c_end). Accumulates A(hi+lo) @ W^T.
// 16 warps: warp (wr,wc) owns output rows [wr*16,+16), cols [wc*32,+32).
// Staging: thread covers 16 halves (TWO uint4) of row lrow, term term_t:
//   term_t = tid>>8, lrow = (tid>>2)&63, lseg = tid&3  (halves [lseg*16, lseg*16+16))
// Coverage: 512 thr x 16 halves = 8192 halves = 2 terms x 64 rows x 64 cols. EXACT.
__device__ __forceinline__ void mma_chunks(
    wmma::fragment<wmma::accumulator, 16, 16, 16, float> (&acc)[2],
    const __half* __restrict__ gact_p,   // &g_act[p][0][0][0]; term stride = BATCH*KACT
    __half* __restrict__ Ast,            // [2 buf][2 term][64][APAD]
    const __half* __restrict__ Wsm,
    int row0, int wr, int wc, int term_t, int lrow, int lseg,
    int c_begin, int c_end)
{
    const __half* src = gact_p + (size_t)term_t * (BATCH*KACT)
                               + (size_t)(row0 + lrow) * KACT + lseg*16;
    __half* dst = Ast + (term_t*64 + lrow)*APAD + lseg*16;

    // stage chunk c_begin into buf 0 (16 halves = 2 x uint4)
    {
        uint4 v0 = ldcg4(src + c_begin*CHUNK);
        uint4 v1 = ldcg4(src + c_begin*CHUNK + 8);
        uint4* d = reinterpret_cast<uint4*>(dst);
        d[0] = v0; d[1] = v1;
    }
    __syncthreads();

    int buf = 0;
    for (int cc = c_begin; cc < c_end; cc++) {
        uint4 p0, p1;
        const bool hn = (cc + 1 < c_end);
        if (hn) {
            p0 = ldcg4(src + (cc+1)*CHUNK);
            p1 = ldcg4(src + (cc+1)*CHUNK + 8);
        }

        const __half* Ab = Ast + buf * (2 * 64 * APAD);
        const int kbase = cc * CHUNK;
        #pragma unroll
        for (int kt = 0; kt < 4; kt++) {
            wmma::fragment<wmma::matrix_b, 16, 16, 16, __half, wmma::col_major> bf[2];
            #pragma unroll
            for (int j = 0; j < 2; j++)
                wmma::load_matrix_sync(bf[j], Wsm + (wc*32 + j*16)*WPAD + kbase + kt*16, WPAD);
            #pragma unroll
            for (int term = 0; term < 2; term++) {
                wmma::fragment<wmma::matrix_a, 16, 16, 16, __half, wmma::row_major> af;
                wmma::load_matrix_sync(af, Ab + (term*64 + wr*16)*APAD + kt*16, APAD);
                #pragma unroll
                for (int j = 0; j < 2; j++)
                    wmma::mma_sync(acc[j], af, bf[j], acc[j]);
            }
        }
        if (hn) {
            buf ^= 1;
            uint4* d = reinterpret_cast<uint4*>(
                Ast + buf*(2*64*APAD) + (term_t*64 + lrow)*APAD + lseg*16);
            d[0] = p0; d[1] = p1;
        }
        __syncthreads();
    }
}

__global__ void __launch_bounds__(NTHREADS, 1)
decoder_kernel(
    const float* __restrict__ x,    const float* __restrict__ h0,
    const float* __restrict__ c0,   const float* __restrict__ W_ih,
    const float* __restrict__ W_hh, const float* __restrict__ b_ih,
    const float* __restrict__ b_hh, const float* __restrict__ fc_W,
    const float* __restrict__ fc_b, float* __restrict__ out)
{
    extern __shared__ unsigned char smem_raw[];
    __half* Wsm  = (__half*)smem_raw;                            // [128][WPAD]
    __half* FCsm = Wsm + 128*WPAD;                               // [128][FPAD]
    __half* Ast  = FCsm + 128*FPAD;                              // R: [2][2][64][APAD]
    float*  gsm  = (float*)Ast;                                  // R: [64][GPAD] (aliased)
    __half* Hloc = (__half*)(smem_raw + 165888 + 10240 + 36864); // [2][64][FPAD]
    float*  csm  = (float*)(Hloc + 2*64*FPAD);                   // [64][32]
    float*  bsm  = csm + 64*32;                                  // [128]

    const int tid  = threadIdx.x;
    const int gid  = blockIdx.x / GCTAS;
    const int rk   = blockIdx.x % GCTAS;
    const int row0 = gid * MB;
    const int hs   = rk * HS;

    const int wid = tid >> 5;
    const int wr  = wid >> 2;        // 0..3 : 16 output rows each
    const int wc  = wid & 3;         // 0..3 : 32 output cols each
    const int term_t = tid >> 8;     // 0..1 : staged term
    const int lrow   = (tid >> 2) & 63;
    const int lseg   = tid & 3;

    // ---------------- init (once) ----------------
    for (int idx = tid; idx < 128*KACT; idx += NTHREADS) {
        int r = idx / KACT, k = idx - r*KACT;
        int q = r >> 5, j = r & 31;
        int grow = q*HDIM + hs + j;
        float v = (k < HDIM) ? W_hh[grow*HDIM + k] : W_ih[grow*IDIM + (k - HDIM)];
        Wsm[r*WPAD + k] = __float2half_rn(v);
    }
    for (int idx = tid; idx < 128*HS; idx += NTHREADS) {
        int n = idx / HS, k = idx - n*HS;
        FCsm[n*FPAD + k] = __float2half_rn(fc_W[n*HDIM + hs + k]);
    }
    for (int r = tid; r < 128; r += NTHREADS) {
        int q = r >> 5, j = r & 31;
        bsm[r] = b_ih[q*HDIM + hs + j] + b_hh[q*HDIM + hs + j];
    }
    for (int idx = tid; idx < MB*HS; idx += NTHREADS) {
        int m = idx >> 5, j = idx & 31;
        csm[m*HS + j] = c0[(row0+m)*HDIM + hs + j];
    }
    for (int idx = tid; idx < MB*HS; idx += NTHREADS) {
        int m = idx >> 5, j = idx & 31;
        float v = h0[(row0+m)*HDIM + hs + j];
        __half hi = __float2half_rn(v);
        __half lo = __float2half_rn(v - __half2float(hi));
        g_act[0][0][row0+m][hs+j] = hi;
        g_act[0][1][row0+m][hs+j] = lo;
    }
    for (int idx = tid; idx < MB*8; idx += NTHREADS) {
        int m = idx >> 3, ccol = rk*8 + (idx & 7);
        float v = x[(TSTEPS-1)*BATCH*IDIM + (row0+m)*IDIM + ccol];
        __half hi = __float2half_rn(v);
        __half lo = __float2half_rn(v - __half2float(hi));
        g_act[0][0][row0+m][HDIM+ccol] = hi;
        g_act[0][1][row0+m][HDIM+ccol] = lo;
    }

    unsigned tgt = GCTAS;
    bar_arrive(gid);
    bar_wait(gid, tgt);     // seeds visible group-wide

    // ---------------- prologue: gates(0) ----------------
    {
        wmma::fragment<wmma::accumulator, 16, 16, 16, float> acc[2];
        wmma::fill_fragment(acc[0], 0.0f);
        wmma::fill_fragment(acc[1], 0.0f);
        mma_chunks(acc, &g_act[0][0][0][0], Ast, Wsm, row0, wr, wc,
                   term_t, lrow, lseg, 0, NCHUNK);
        #pragma unroll
        for (int j = 0; j < 2; j++)
            wmma::store_matrix_sync(&gsm[(wr*16)*GPAD + wc*32 + j*16],
                                    acc[j], GPAD, wmma::mem_row_major);
        __syncthreads();
    }

    // ---------------- 512 sequential steps ----------------
    for (int t = 0; t < TSTEPS; t++) {
        const int pn = (t + 1) & 1;
        const bool more = (t < TSTEPS - 1);

        // ===== pointwise LSTM: gsm -> h_new (global pn + Hloc) =====
        #pragma unroll
        for (int it = 0; it < (MB*HS)/NTHREADS; it++) {
            int idx = tid + it*NTHREADS;
            int m = idx >> 5, j = idx & 31;
            float zi = gsm[m*GPAD +      j] + bsm[     j];
            float zf = gsm[m*GPAD + 32 + j] + bsm[32 + j];
            float zg = gsm[m*GPAD + 64 + j] + bsm[64 + j];
            float zo = gsm[m*GPAD + 96 + j] + bsm[96 + j];
            float c  = csm[m*HS + j];
            float ig = fsigmoid(zi);
            float fg = fsigmoid(zf);
            float gg = ftanh_(zg);
            float og = fsigmoid(zo);
            float cn = fg*c + ig*gg;
            float hn = og * ftanh_(cn);
            csm[m*HS + j] = cn;
            __half hi = __float2half_rn(hn);
            __half lo = __float2half_rn(hn - __half2float(hi));
            g_act[pn][0][row0+m][hs+j] = hi;
            g_act[pn][1][row0+m][hs+j] = lo;
            Hloc[(0*64 + m)*FPAD + j] = hi;
            Hloc[(1*64 + m)*FPAD + j] = lo;
        }
        __syncthreads();   // Hloc ready; gsm dead

        // ===== fc partial: [64 x 128] = (h_hi+h_lo)[64x32] @ fc_W_slice^T =====
        {
            wmma::fragment<wmma::accumulator, 16, 16, 16, float> pacc[2];
            wmma::fill_fragment(pacc[0], 0.0f);
            wmma::fill_fragment(pacc[1], 0.0f);
            #pragma unroll
            for (int tt = 0; tt < 2; tt++) {
                #pragma unroll
                for (int kt = 0; kt < 2; kt++) {
                    wmma::fragment<wmma::matrix_b, 16, 16, 16, __half, wmma::col_major> bf[2];
                    #pragma unroll
                    for (int j = 0; j < 2; j++)
                        wmma::load_matrix_sync(bf[j], FCsm + (wc*32 + j*16)*FPAD + kt*16, FPAD);
                    wmma::fragment<wmma::matrix_a, 16, 16, 16, __half, wmma::row_major> af;
                    wmma::load_matrix_sync(af, Hloc + (tt*64 + wr*16)*FPAD + kt*16, FPAD);
                    #pragma unroll
                    for (int j = 0; j < 2; j++)
                        wmma::mma_sync(pacc[j], af, bf[j], pacc[j]);
                }
            }
            float* base = &g_fcpart[((gid*GCTAS + rk)*MB)*IDIM];
            #pragma unroll
            for (int j = 0; j < 2; j++)
                wmma::store_matrix_sync(base + (wr*16)*IDIM + wc*32 + j*16,
                                        pacc[j], IDIM, wmma::mem_row_major);
        }

        bar_arrive(gid);                 // A: h_new + fc partials published
        tgt += GCTAS;
        bar_wait(gid, tgt);              // (only exposed barrier; skew only)

        // ===== finalize fc cols [rk*8, rk*8+8): reduce, activate, feedback =====
        {
            int m = tid >> 3, n = rk*8 + (tid & 7);
            float z = fc_b[n];
            #pragma unroll
            for (int s = 0; s < GCTAS; s++)
                z += __ldcg(&g_fcpart[((gid*GCTAS + s)*MB + m)*IDIM + n]);
            float y = ftanh_(0.5f * z);   // == 2*sigmoid(z) - 1
            out[(TSTEPS-1-t)*BATCH*IDIM + (row0+m)*IDIM + n] = y;
            __half hi = __float2half_rn(y);
            __half lo = __float2half_rn(y - __half2float(hi));
            g_act[pn][0][row0+m][HDIM+n] = hi;
            g_act[pn][1][row0+m][HDIM+n] = lo;
        }

        bar_arrive(gid);                 // B: inp(t+1) published
        tgt += GCTAS;

        if (more) {
            // ===== gates(t+1): part1 over h chunks (hides barrier B latency) =====
            wmma::fragment<wmma::accumulator, 16, 16, 16, float> acc[2];
            wmma::fill_fragment(acc[0], 0.0f);
            wmma::fill_fragment(acc[1], 0.0f);
            const __half* gp = &g_act[pn][0][0][0];
            mma_chunks(acc, gp, Ast, Wsm, row0, wr, wc, term_t, lrow, lseg, 0, HCHUNK);

            bar_wait(gid, tgt);          // B: should already be satisfied

            mma_chunks(acc, gp, Ast, Wsm, row0, wr, wc, term_t, lrow, lseg, HCHUNK, NCHUNK);

            #pragma unroll
            for (int j = 0; j < 2; j++)
                wmma::store_matrix_sync(&gsm[(wr*16)*GPAD + wc*32 + j*16],
                                        acc[j], GPAD, wmma::mem_row_major);
            __syncthreads();
        } else {
            bar_wait(gid, tgt);          // keep targets consistent
        }
    }
}

extern "C" void kernel_launch(void* const* d_in, const int* in_sizes, int n_in,
                              void* d_out, int out_size)
{
    const float* x    = (const float*)d_in[0];
    // d_in[1] = enc_hiddens : unused by the reference recursion
    const float* h0   = (const float*)d_in[2];
    const float* c0   = (const float*)d_in[3];
    const float* W_ih = (const float*)d_in[4];
    const float* W_hh = (const float*)d_in[5];
    const float* b_ih = (const float*)d_in[6];
    const float* b_hh = (const float*)d_in[7];
    const float* fc_W = (const float*)d_in[8];
    const float* fc_b = (const float*)d_in[9];
    float* out = (float*)d_out;

    cudaFuncSetAttribute(decoder_kernel, cudaFuncAttributeMaxDynamicSharedMemorySize, SMEM_BYTES);

    // Reset group-barrier counters every replay (captured memset node)
    void* barp = nullptr;
    cudaGetSymbolAddress(&barp, g_bar);
    cudaMemsetAsync(barp, 0, sizeof(unsigned) * NGROUPS);

    decoder_kernel<<<NCTA, NTHREADS, SMEM_BYTES>>>(x, h0, c0, W_ih, W_hh,
                                                   b_ih, b_hh, fc_W, fc_b, out);
}

// round 8
// speedup vs baseline: 2.3193x; 1.8702x over previous
#include <cuda_runtime.h>
#include <cuda_fp16.h>
#include <mma.h>
#include <cstdint>
#include <math.h>

using namespace nvcuda;

// Problem constants
#define TSTEPS 512
#define BATCH  512
#define IDIM   128
#define HDIM   512
#define KACT   640   // reordered: cols [0,512)=h, [512,640)=inp

// Partitioning: 8 batch-groups x 16 CTAs = 128 CTAs (1 per SM, one wave)
#define NGROUPS 8
#define GCTAS   16
#define NCTA    (NGROUPS*GCTAS)
#define MB      64
#define HS      32
#define NTHREADS 256   // 8 warps: 2 warp-rows x 4 warp-cols (32x32 tiles) -- proven best

// SMEM padding / tiling
#define WPAD 648      // weight row stride (halfs)
#define FPAD 40       // Hloc / fc-weight row stride (halfs)
#define GPAD 132      // gates staging row stride (floats)
#define APAD 136      // A-stage row stride (halfs); 272B rows -> +16B offset/row mod 128B
#define CHUNK 128     // K columns per staged chunk (single term now)
#define NCHUNK 5      // 640 / 128
#define HCHUNK 4      // chunks [0,4) = h region [0,512); chunk 4 = inp [512,640)

// SMEM layout (bytes):
//  Wsm  128*WPAD*2              = 165888   @ 0
//  FCsm 128*FPAD*2              =  10240   @ 165888
//  R    max(gsm 64*GPAD*4=33792, Ast 2*64*APAD*2=34816) = 34816 @ 176128 (aliased)
//  Hloc 64*FPAD*2               =   5120   @ 210944
//  csm  64*32*4                 =   8192   @ 216064
//  bsm  128*4                   =    512   @ 224256
#define SMEM_BYTES 224768

// Global state (single-term fp16 activations, double-buffered by step parity)
__device__ __align__(16) __half g_act[2][BATCH][KACT];   // [parity][row][col]
__device__ float g_fcpart[NGROUPS*GCTAS*MB*IDIM];
__device__ unsigned g_bar[NGROUPS];                       // monotonic barrier counters

__device__ __forceinline__ void bar_arrive(int gid) {
    if (threadIdx.x == 0) {
        __threadfence();                 // release my global writes
        atomicAdd(&g_bar[gid], 1u);
    }
}
__device__ __forceinline__ void bar_wait(int gid, unsigned target) {
    if (threadIdx.x == 0) {
        while (*((volatile unsigned*)&g_bar[gid]) < target) { __nanosleep(20); }
        __threadfence();                 // acquire others' global writes
    }
    __syncthreads();
}

__device__ __forceinline__ uint4 ldcg4(const void* p) {
    return __ldcg(reinterpret_cast<const uint4*>(p));
}

// Overflow-safe fast sigmoid/tanh (EX2+RCP MUFU path, rel err ~2^-21)
__device__ __forceinline__ float fsigmoid(float z) {
    float e = __expf(-fabsf(z));
    float num = (z >= 0.f) ? 1.f : e;
    return __fdividef(num, 1.f + e);
}
__device__ __forceinline__ float ftanh_(float z) {
    float e = __expf(-2.f * fabsf(z));
    float r = __fdividef(1.f - e, 1.f + e);
    return (z >= 0.f) ? r : -r;
}

// Staged-chunk MMA over chunks [c_begin, c_end). Accumulates A @ W^T (single term).
// 8 warps: warp (wr,wc) owns output rows [wr*32,+32), cols [wc*32,+32).
// Staging per chunk: 64 rows x 128 halves. Thread covers 32 halves (FOUR uint4):
//   lrow = tid>>2 (0..63), lseg = tid&3  (halves [lseg*32, lseg*32+32))
// Coverage: 256 thr x 32 halves = 8192 = 64 x 128. EXACT.
__device__ __forceinline__ void mma_chunks(
    wmma::fragment<wmma::accumulator, 16, 16, 16, float> (&acc)[2][2],
    const __half* __restrict__ gact_p,   // &g_act[p][0][0]
    __half* __restrict__ Ast,            // [2 buf][64][APAD]
    const __half* __restrict__ Wsm,
    int row0, int wr, int wc, int lrow, int lseg,
    int c_begin, int c_end)
{
    const __half* src = gact_p + (size_t)(row0 + lrow) * KACT + lseg*32;
    __half* dst0 = Ast + lrow*APAD + lseg*32;

    // stage chunk c_begin into buf 0 (32 halves = 4 x uint4)
    {
        const __half* s = src + c_begin*CHUNK;
        uint4 v0 = ldcg4(s);
        uint4 v1 = ldcg4(s + 8);
        uint4 v2 = ldcg4(s + 16);
        uint4 v3 = ldcg4(s + 24);
        uint4* d = reinterpret_cast<uint4*>(dst0);
        d[0] = v0; d[1] = v1; d[2] = v2; d[3] = v3;
    }
    __syncthreads();

    int buf = 0;
    for (int cc = c_begin; cc < c_end; cc++) {
        uint4 p0, p1, p2, p3;
        const bool hn = (cc + 1 < c_end);
        if (hn) {
            const __half* s = src + (cc+1)*CHUNK;
            p0 = ldcg4(s);
            p1 = ldcg4(s + 8);
            p2 = ldcg4(s + 16);
            p3 = ldcg4(s + 24);
        }

        const __half* Ab = Ast + buf * (64 * APAD);
        const int kbase = cc * CHUNK;
        #pragma unroll
        for (int kt = 0; kt < 8; kt++) {
            wmma::fragment<wmma::matrix_b, 16, 16, 16, __half, wmma::col_major> bf[2];
            #pragma unroll
            for (int j = 0; j < 2; j++)
                wmma::load_matrix_sync(bf[j], Wsm + (wc*32 + j*16)*WPAD + kbase + kt*16, WPAD);
            #pragma unroll
            for (int i = 0; i < 2; i++) {
                wmma::fragment<wmma::matrix_a, 16, 16, 16, __half, wmma::row_major> af;
                wmma::load_matrix_sync(af, Ab + (wr*32 + i*16)*APAD + kt*16, APAD);
                #pragma unroll
                for (int j = 0; j < 2; j++)
                    wmma::mma_sync(acc[i][j], af, bf[j], acc[i][j]);
            }
        }
        if (hn) {
            buf ^= 1;
            uint4* d = reinterpret_cast<uint4*>(Ast + buf*(64*APAD) + lrow*APAD + lseg*32);
            d[0] = p0; d[1] = p1; d[2] = p2; d[3] = p3;
        }
        __syncthreads();
    }
}

__global__ void __launch_bounds__(NTHREADS, 1)
decoder_kernel(
    const float* __restrict__ x,    const float* __restrict__ h0,
    const float* __restrict__ c0,   const float* __restrict__ W_ih,
    const float* __restrict__ W_hh, const float* __restrict__ b_ih,
    const float* __restrict__ b_hh, const float* __restrict__ fc_W,
    const float* __restrict__ fc_b, float* __restrict__ out)
{
    extern __shared__ unsigned char smem_raw[];
    __half* Wsm  = (__half*)smem_raw;                        // [128][WPAD]
    __half* FCsm = Wsm + 128*WPAD;                           // [128][FPAD]
    __half* Ast  = FCsm + 128*FPAD;                          // R: [2][64][APAD]
    float*  gsm  = (float*)Ast;                              // R: [64][GPAD] (aliased)
    __half* Hloc = (__half*)(smem_raw + 210944);             // [64][FPAD]
    float*  csm  = (float*)(smem_raw + 216064);              // [64][32]
    float*  bsm  = (float*)(smem_raw + 224256);              // [128]

    const int tid  = threadIdx.x;
    const int gid  = blockIdx.x / GCTAS;
    const int rk   = blockIdx.x % GCTAS;
    const int row0 = gid * MB;
    const int hs   = rk * HS;

    const int wid = tid >> 5;
    const int wr  = wid >> 2;        // 0..1 : 32 output rows each
    const int wc  = wid & 3;         // 0..3 : 32 output cols each
    const int lrow = tid >> 2;       // 0..63
    const int lseg = tid & 3;        // 0..3

    // ---------------- init (once) ----------------
    // Weights, K-reordered: col k<512 -> W_hh[.,k]; k>=512 -> W_ih[., k-512]
    for (int idx = tid; idx < 128*KACT; idx += NTHREADS) {
        int r = idx / KACT, k = idx - r*KACT;
        int q = r >> 5, j = r & 31;
        int grow = q*HDIM + hs + j;
        float v = (k < HDIM) ? W_hh[grow*HDIM + k] : W_ih[grow*IDIM + (k - HDIM)];
        Wsm[r*WPAD + k] = __float2half_rn(v);
    }
    for (int idx = tid; idx < 128*HS; idx += NTHREADS) {
        int n = idx / HS, k = idx - n*HS;
        FCsm[n*FPAD + k] = __float2half_rn(fc_W[n*HDIM + hs + k]);
    }
    for (int r = tid; r < 128; r += NTHREADS) {
        int q = r >> 5, j = r & 31;
        bsm[r] = b_ih[q*HDIM + hs + j] + b_hh[q*HDIM + hs + j];
    }
    for (int idx = tid; idx < MB*HS; idx += NTHREADS) {
        int m = idx >> 5, j = idx & 31;
        csm[m*HS + j] = c0[(row0+m)*HDIM + hs + j];
    }
    // seed g_act parity 0: h at cols [hs,hs+32), inp at cols [512+rk*8, ...)
    for (int idx = tid; idx < MB*HS; idx += NTHREADS) {
        int m = idx >> 5, j = idx & 31;
        g_act[0][row0+m][hs+j] = __float2half_rn(h0[(row0+m)*HDIM + hs + j]);
    }
    for (int idx = tid; idx < MB*8; idx += NTHREADS) {
        int m = idx >> 3, ccol = rk*8 + (idx & 7);
        g_act[0][row0+m][HDIM+ccol] =
            __float2half_rn(x[(TSTEPS-1)*BATCH*IDIM + (row0+m)*IDIM + ccol]);
    }

    unsigned tgt = GCTAS;
    bar_arrive(gid);
    bar_wait(gid, tgt);     // seeds visible group-wide

    // ---------------- prologue: gates(0) ----------------
    {
        wmma::fragment<wmma::accumulator, 16, 16, 16, float> acc[2][2];
        #pragma unroll
        for (int i = 0; i < 2; i++)
            #pragma unroll
            for (int j = 0; j < 2; j++)
                wmma::fill_fragment(acc[i][j], 0.0f);
        mma_chunks(acc, &g_act[0][0][0], Ast, Wsm, row0, wr, wc, lrow, lseg, 0, NCHUNK);
        #pragma unroll
        for (int i = 0; i < 2; i++)
            #pragma unroll
            for (int j = 0; j < 2; j++)
                wmma::store_matrix_sync(&gsm[(wr*32 + i*16)*GPAD + wc*32 + j*16],
                                        acc[i][j], GPAD, wmma::mem_row_major);
        __syncthreads();
    }

    // ---------------- 512 sequential steps ----------------
    for (int t = 0; t < TSTEPS; t++) {
        const int pn = (t + 1) & 1;
        const bool more = (t < TSTEPS - 1);

        // ===== pointwise LSTM: gsm -> h_new (global pn + Hloc) =====
        #pragma unroll
        for (int it = 0; it < (MB*HS)/NTHREADS; it++) {
            int idx = tid + it*NTHREADS;
            int m = idx >> 5, j = idx & 31;
            float zi = gsm[m*GPAD +      j] + bsm[     j];
            float zf = gsm[m*GPAD + 32 + j] + bsm[32 + j];
            float zg = gsm[m*GPAD + 64 + j] + bsm[64 + j];
            float zo = gsm[m*GPAD + 96 + j] + bsm[96 + j];
            float c  = csm[m*HS + j];
            float ig = fsigmoid(zi);
            float fg = fsigmoid(zf);
            float gg = ftanh_(zg);
            float og = fsigmoid(zo);
            float cn = fg*c + ig*gg;
            float hn = og * ftanh_(cn);
            csm[m*HS + j] = cn;
            __half hh = __float2half_rn(hn);
            g_act[pn][row0+m][hs+j] = hh;
            Hloc[m*FPAD + j] = hh;
        }
        __syncthreads();   // Hloc ready; gsm dead (R reusable)

        // ===== fc partial: [64 x 128] = h_slice[64x32] @ fc_W_slice^T =====
        {
            wmma::fragment<wmma::accumulator, 16, 16, 16, float> pacc[2][2];
            #pragma unroll
            for (int i = 0; i < 2; i++)
                #pragma unroll
                for (int j = 0; j < 2; j++)
                    wmma::fill_fragment(pacc[i][j], 0.0f);
            #pragma unroll
            for (int kt = 0; kt < 2; kt++) {
                wmma::fragment<wmma::matrix_b, 16, 16, 16, __half, wmma::col_major> bf[2];
                #pragma unroll
                for (int j = 0; j < 2; j++)
                    wmma::load_matrix_sync(bf[j], FCsm + (wc*32 + j*16)*FPAD + kt*16, FPAD);
                #pragma unroll
                for (int i = 0; i < 2; i++) {
                    wmma::fragment<wmma::matrix_a, 16, 16, 16, __half, wmma::row_major> af;
                    wmma::load_matrix_sync(af, Hloc + (wr*32 + i*16)*FPAD + kt*16, FPAD);
                    #pragma unroll
                    for (int j = 0; j < 2; j++)
                        wmma::mma_sync(pacc[i][j], af, bf[j], pacc[i][j]);
                }
            }
            float* base = &g_fcpart[((gid*GCTAS + rk)*MB)*IDIM];
            #pragma unroll
            for (int i = 0; i < 2; i++)
                #pragma unroll
                for (int j = 0; j < 2; j++)
                    wmma::store_matrix_sync(base + (wr*32 + i*16)*IDIM + wc*32 + j*16,
                                            pacc[i][j], IDIM, wmma::mem_row_major);
        }

        bar_arrive(gid);                 // A: h_new + fc partials published
        tgt += GCTAS;
        bar_wait(gid, tgt);              // (only exposed barrier; symmetric skew)

        // ===== finalize fc cols [rk*8, rk*8+8): reduce, activate, feedback =====
        #pragma unroll
        for (int it = 0; it < (MB*8)/NTHREADS; it++) {
            int idx = tid + it*NTHREADS;
            int m = idx >> 3, n = rk*8 + (idx & 7);
            float z = fc_b[n];
            #pragma unroll
            for (int s = 0; s < GCTAS; s++)
                z += __ldcg(&g_fcpart[((gid*GCTAS + s)*MB + m)*IDIM + n]);
            float y = ftanh_(0.5f * z);   // == 2*sigmoid(z) - 1
            out[(TSTEPS-1-t)*BATCH*IDIM + (row0+m)*IDIM + n] = y;
            g_act[pn][row0+m][HDIM+n] = __float2half_rn(y);
        }

        bar_arrive(gid);                 // B: inp(t+1) published
        tgt += GCTAS;

        if (more) {
            // ===== gates(t+1): part1 over h chunks (hides barrier B latency) =====
            wmma::fragment<wmma::accumulator, 16, 16, 16, float> acc[2][2];
            #pragma unroll
            for (int i = 0; i < 2; i++)
                #pragma unroll
                for (int j = 0; j < 2; j++)
                    wmma::fill_fragment(acc[i][j], 0.0f);
            const __half* gp = &g_act[pn][0][0];
            mma_chunks(acc, gp, Ast, Wsm, row0, wr, wc, lrow, lseg, 0, HCHUNK);

            bar_wait(gid, tgt);          // B: should already be satisfied

            mma_chunks(acc, gp, Ast, Wsm, row0, wr, wc, lrow, lseg, HCHUNK, NCHUNK);

            #pragma unroll
            for (int i = 0; i < 2; i++)
                #pragma unroll
                for (int j = 0; j < 2; j++)
                    wmma::store_matrix_sync(&gsm[(wr*32 + i*16)*GPAD + wc*32 + j*16],
                                            acc[i][j], GPAD, wmma::mem_row_major);
            __syncthreads();
        } else {
            bar_wait(gid, tgt);          // keep targets consistent
        }
    }
}

extern "C" void kernel_launch(void* const* d_in, const int* in_sizes, int n_in,
                              void* d_out, int out_size)
{
    const float* x    = (const float*)d_in[0];
    // d_in[1] = enc_hiddens : unused by the reference recursion
    const float* h0   = (const float*)d_in[2];
    const float* c0   = (const float*)d_in[3];
    const float* W_ih = (const float*)d_in[4];
    const float* W_hh = (const float*)d_in[5];
    const float* b_ih = (const float*)d_in[6];
    const float* b_hh = (const float*)d_in[7];
    const float* fc_W = (const float*)d_in[8];
    const float* fc_b = (const float*)d_in[9];
    float* out = (float*)d_out;

    cudaFuncSetAttribute(decoder_kernel, cudaFuncAttributeMaxDynamicSharedMemorySize, SMEM_BYTES);

    // Reset group-barrier counters every replay (captured memset node)
    void* barp = nullptr;
    cudaGetSymbolAddress(&barp, g_bar);
    cudaMemsetAsync(barp, 0, sizeof(unsigned) * NGROUPS);

    decoder_kernel<<<NCTA, NTHREADS, SMEM_BYTES>>>(x, h0, c0, W_ih, W_hh,
                                                   b_ih, b_hh, fc_W, fc_b, out);
}

// round 10
// speedup vs baseline: 2.4472x; 1.0552x over previous
#include <cuda_runtime.h>
#include <cuda_fp16.h>
#include <mma.h>
#include <cstdint>
#include <math.h>

using namespace nvcuda;

// Problem constants
#define TSTEPS 512
#define BATCH  512
#define IDIM   128
#define HDIM   512
#define KACT   640   // reordered: cols [0,512)=h, [512,640)=inp

// Partitioning: 8 batch-groups x 16 CTAs = 128 CTAs (1 per SM, one wave)
#define NGROUPS 8
#define GCTAS   16
#define NCTA    (NGROUPS*GCTAS)
#define MB      64
#define HS      32
#define NTHREADS 256   // 8 warps: 2 warp-rows x 4 warp-cols (32x32 gate tiles)

// Extended N: 128 gate cols + 16 fc cols (8 real + 8 zero-pad)
#define NROWS 144

// SMEM padding / tiling
#define WPAD 648      // weight row stride (halfs)
#define GPAD 132      // gates staging row stride (floats)
#define APAD 136      // A-stage row stride (halfs)
#define CHUNK 128     // K columns per staged chunk
#define NCHUNK 5      // 640 / 128
#define HCHUNK 4      // chunks [0,4) = h region [0,512); chunk 4 = inp [512,640)
#define F2P  18       // fcz buffer pitch (floats)

// SMEM layout (bytes):
//  Wsm  144*WPAD*2 = 186624   @ 0        (rows 0..127 gates, 128..143 fc+zeropad)
//  R    max(Ast 2*64*APAD*2=34816, gsm 64*GPAD*4=33792) = 34816 @ 186624 (aliased)
//  fczb 64*F2P*4   = 4608     @ 221440
//  bsm  128*4      = 512      @ 226048
//  fcbs 8*4        = 32       @ 226560
#define SMEM_BYTES 226816

// Global state
__device__ __align__(16) __half g_act[2][BATCH][KACT];   // [parity][row][col]
__device__ unsigned g_bar[NGROUPS];                       // monotonic barrier counters

// ---------------- barriers (release-atomic + acquire-fence spin) ----------------
__device__ __forceinline__ void bar_arrive(const unsigned* barp) {
    if (threadIdx.x == 0) {
        asm volatile("red.release.gpu.global.add.u32 [%0], %1;"
                     :: "l"(barp), "r"(1u) : "memory");
    }
}
__device__ __forceinline__ void bar_wait(const unsigned* barp, unsigned target) {
    if (threadIdx.x == 0) {
        unsigned v;
        do {
            asm volatile("ld.relaxed.gpu.global.u32 %0, [%1];" : "=r"(v) : "l"(barp));
        } while (v < target);
        asm volatile("fence.acq_rel.gpu;" ::: "memory");
    }
    __syncthreads();
}

__device__ __forceinline__ uint4 ldcg4(const void* p) {
    return __ldcg(reinterpret_cast<const uint4*>(p));
}

// Overflow-safe fast sigmoid/tanh (EX2+RCP MUFU path, rel err ~2^-21)
__device__ __forceinline__ float fsigmoid(float z) {
    float e = __expf(-fabsf(z));
    float num = (z >= 0.f) ? 1.f : e;
    return __fdividef(num, 1.f + e);
}
__device__ __forceinline__ float ftanh_(float z) {
    float e = __expf(-2.f * fabsf(z));
    float r = __fdividef(1.f - e, 1.f + e);
    return (z >= 0.f) ? r : -r;
}

// Staged-chunk MMA over chunks [c_begin, c_end). Accumulates act @ W^T.
// 8 warps: warp (wr,wc) owns gate rows [wr*32,+32) x cols [wc*32,+32).
// do_fc warps additionally accumulate the fc tile (Wsm rows 128..143).
// Staging per chunk: 64 rows x 128 halves; thread = 4 uint4 (lrow=tid>>2, lseg=tid&3).
__device__ __forceinline__ void mma_chunks(
    wmma::fragment<wmma::accumulator, 16, 16, 16, float> (&acc)[2][2],
    wmma::fragment<wmma::accumulator, 16, 16, 16, float> (&accfc)[2],
    const __half* __restrict__ gact_p,
    __half* __restrict__ Ast,            // [2 buf][64][APAD]
    const __half* __restrict__ Wsm,
    int row0, int wr, int wc, int lrow, int lseg,
    int c_begin, int c_end, bool do_fc)
{
    const __half* src = gact_p + (size_t)(row0 + lrow) * KACT + lseg*32;

    // stage chunk c_begin into buf 0 (32 halves = 4 x uint4)
    {
        const __half* s = src + c_begin*CHUNK;
        uint4 v0 = ldcg4(s);
        uint4 v1 = ldcg4(s + 8);
        uint4 v2 = ldcg4(s + 16);
        uint4 v3 = ldcg4(s + 24);
        uint4* d = reinterpret_cast<uint4*>(Ast + lrow*APAD + lseg*32);
        d[0] = v0; d[1] = v1; d[2] = v2; d[3] = v3;
    }
    __syncthreads();

    int buf = 0;
    for (int cc = c_begin; cc < c_end; cc++) {
        uint4 p0, p1, p2, p3;
        const bool hn = (cc + 1 < c_end);
        if (hn) {
            const __half* s = src + (cc+1)*CHUNK;
            p0 = ldcg4(s);
            p1 = ldcg4(s + 8);
            p2 = ldcg4(s + 16);
            p3 = ldcg4(s + 24);
        }

        const __half* Ab = Ast + buf * (64 * APAD);
        const int kbase = cc * CHUNK;
        #pragma unroll
        for (int kt = 0; kt < 8; kt++) {
            wmma::fragment<wmma::matrix_a, 16, 16, 16, __half, wmma::row_major> af[2];
            #pragma unroll
            for (int i = 0; i < 2; i++)
                wmma::load_matrix_sync(af[i], Ab + (wr*32 + i*16)*APAD + kt*16, APAD);
            #pragma unroll
            for (int j = 0; j < 2; j++) {
                wmma::fragment<wmma::matrix_b, 16, 16, 16, __half, wmma::col_major> bf;
                wmma::load_matrix_sync(bf, Wsm + (wc*32 + j*16)*WPAD + kbase + kt*16, WPAD);
                #pragma unroll
                for (int i = 0; i < 2; i++)
                    wmma::mma_sync(acc[i][j], af[i], bf, acc[i][j]);
            }
            if (do_fc) {
                wmma::fragment<wmma::matrix_b, 16, 16, 16, __half, wmma::col_major> bffc;
                wmma::load_matrix_sync(bffc, Wsm + 128*WPAD + kbase + kt*16, WPAD);
                #pragma unroll
                for (int i = 0; i < 2; i++)
                    wmma::mma_sync(accfc[i], af[i], bffc, accfc[i]);
            }
        }
        if (hn) {
            buf ^= 1;
            uint4* d = reinterpret_cast<uint4*>(Ast + buf*(64*APAD) + lrow*APAD + lseg*32);
            d[0] = p0; d[1] = p1; d[2] = p2; d[3] = p3;
        }
        __syncthreads();
    }
}

__global__ void __launch_bounds__(NTHREADS, 1)
decoder_kernel(
    const float* __restrict__ x,    const float* __restrict__ h0,
    const float* __restrict__ c0,   const float* __restrict__ W_ih,
    const float* __restrict__ W_hh, const float* __restrict__ b_ih,
    const float* __restrict__ b_hh, const float* __restrict__ fc_W,
    const float* __restrict__ fc_b, float* __restrict__ out)
{
    extern __shared__ unsigned char smem_raw[];
    __half* Wsm  = (__half*)smem_raw;                        // [144][WPAD]
    __half* Ast  = (__half*)(smem_raw + 186624);             // R: [2][64][APAD]
    float*  gsm  = (float*)(smem_raw + 186624);              // R: [64][GPAD] (aliased)
    float*  fczb = (float*)(smem_raw + 221440);              // [64][F2P]
    float*  bsm  = (float*)(smem_raw + 226048);              // [128]
    float*  fcbs = (float*)(smem_raw + 226560);              // [8]

    const int tid  = threadIdx.x;
    const int gid  = blockIdx.x / GCTAS;
    const int rk   = blockIdx.x % GCTAS;
    const int row0 = gid * MB;
    const int hs   = rk * HS;
    const unsigned* barp = &g_bar[gid];

    const int wid = tid >> 5;
    const int wr  = wid >> 2;        // 0..1 : 32 gate rows (batch m) each
    const int wc  = wid & 3;         // 0..3 : 32 gate cols each
    const int lrow = tid >> 2;       // 0..63
    const int lseg = tid & 3;        // 0..3
    // fc tile carried by wids 3 (SMSP3, m 0..31) and 4 (SMSP0, m 32..63)
    const bool fcw = (wid == 3) || (wid == 4);

    // ---------------- init (once) ----------------
    // Wsm rows 0..127: gates, K-reordered (k<512 -> W_hh, k>=512 -> W_ih)
    // Wsm rows 128..143: fc rows (8 real over K<512, rest zero)
    for (int idx = tid; idx < NROWS*KACT; idx += NTHREADS) {
        int r = idx / KACT, k = idx - r*KACT;
        float v;
        if (r < 128) {
            int q = r >> 5, j = r & 31;
            int grow = q*HDIM + hs + j;
            v = (k < HDIM) ? W_hh[grow*HDIM + k] : W_ih[grow*IDIM + (k - HDIM)];
        } else {
            int ff = r - 128;
            v = (ff < 8 && k < HDIM) ? fc_W[(rk*8 + ff)*HDIM + k] : 0.0f;
        }
        Wsm[r*WPAD + k] = __float2half_rn(v);
    }
    for (int r = tid; r < 128; r += NTHREADS) {
        int q = r >> 5, j = r & 31;
        bsm[r] = b_ih[q*HDIM + hs + j] + b_hh[q*HDIM + hs + j];
    }
    if (tid < 8) fcbs[tid] = fc_b[rk*8 + tid];

    // cell state in registers: element it -> (m = (tid>>5)+it*8, j = tid&31)
    float cr[8];
    #pragma unroll
    for (int it = 0; it < 8; it++) {
        int m = (tid >> 5) + it*8, j = tid & 31;
        cr[it] = c0[(row0+m)*HDIM + hs + j];
    }

    // seed g_act parity 0: h at cols [hs,hs+32), inp at cols [512+rk*8,+8)
    for (int idx = tid; idx < MB*HS; idx += NTHREADS) {
        int m = idx >> 5, j = idx & 31;
        g_act[0][row0+m][hs+j] = __float2half_rn(h0[(row0+m)*HDIM + hs + j]);
    }
    for (int idx = tid; idx < MB*8; idx += NTHREADS) {
        int m = idx >> 3, ccol = rk*8 + (idx & 7);
        g_act[0][row0+m][HDIM+ccol] =
            __float2half_rn(x[(TSTEPS-1)*BATCH*IDIM + (row0+m)*IDIM + ccol]);
    }

    unsigned tgt = GCTAS;
    bar_arrive(barp);
    bar_wait(barp, tgt);     // seeds visible group-wide

    wmma::fragment<wmma::accumulator, 16, 16, 16, float> acc[2][2];
    wmma::fragment<wmma::accumulator, 16, 16, 16, float> accfc[2];

    // ---------------- prologue: gates(0) (fc lanes idle) ----------------
    {
        #pragma unroll
        for (int i = 0; i < 2; i++)
            #pragma unroll
            for (int j = 0; j < 2; j++)
                wmma::fill_fragment(acc[i][j], 0.0f);
        mma_chunks(acc, accfc, &g_act[0][0][0], Ast, Wsm, row0, wr, wc, lrow, lseg,
                   0, NCHUNK, false);
        #pragma unroll
        for (int i = 0; i < 2; i++)
            #pragma unroll
            for (int j = 0; j < 2; j++)
                wmma::store_matrix_sync(&gsm[(wr*32 + i*16)*GPAD + wc*32 + j*16],
                                        acc[i][j], GPAD, wmma::mem_row_major);
        __syncthreads();
    }

    // ---------------- 512 sequential steps ----------------
    for (int t = 0; t < TSTEPS; t++) {
        const int pw = (t + 1) & 1;      // parity holding h_{t+1} / inp_{t+1}
        const bool more = (t < TSTEPS - 1);

        // ===== pointwise LSTM: gsm (gates_t) + cr -> h_{t+1} (global pw) =====
        #pragma unroll
        for (int it = 0; it < 8; it++) {
            int m = (tid >> 5) + it*8, j = tid & 31;
            float zi = gsm[m*GPAD +      j] + bsm[     j];
            float zf = gsm[m*GPAD + 32 + j] + bsm[32 + j];
            float zg = gsm[m*GPAD + 64 + j] + bsm[64 + j];
            float zo = gsm[m*GPAD + 96 + j] + bsm[96 + j];
            float ig = fsigmoid(zi);
            float fg = fsigmoid(zf);
            float gg = ftanh_(zg);
            float og = fsigmoid(zo);
            float cn = fg*cr[it] + ig*gg;
            float hn = og * ftanh_(cn);
            cr[it] = cn;
            g_act[pw][row0+m][hs+j] = __float2half_rn(hn);
        }
        bar_arrive(barp);                // A: h_{t+1} published
        tgt += GCTAS;
        bar_wait(barp, tgt);

        // ===== phase1: gates(t+1) h-part + FULL fcz_t = h_{t+1} @ fc_W^T =====
        #pragma unroll
        for (int i = 0; i < 2; i++) {
            wmma::fill_fragment(accfc[i], 0.0f);
            #pragma unroll
            for (int j = 0; j < 2; j++)
                wmma::fill_fragment(acc[i][j], 0.0f);
        }
        mma_chunks(acc, accfc, &g_act[pw][0][0], Ast, Wsm, row0, wr, wc, lrow, lseg,
                   0, HCHUNK, fcw);
        if (fcw) {
            #pragma unroll
            for (int i = 0; i < 2; i++)
                wmma::store_matrix_sync(&fczb[(wr*32 + i*16)*F2P], accfc[i],
                                        F2P, wmma::mem_row_major);
        }
        __syncthreads();

        // ===== finalize: out_t = tanh(0.5*(fcz+b)); feedback inp_{t+1} =====
        float yv[2]; int mv[2], nv[2];
        #pragma unroll
        for (int it = 0; it < 2; it++) {
            int idx = tid + it*NTHREADS;
            int m = idx >> 3, ff = idx & 7;
            float z = fczb[m*F2P + ff] + fcbs[ff];
            float y = ftanh_(0.5f * z);
            g_act[pw][row0+m][HDIM + rk*8 + ff] = __float2half_rn(y);
            yv[it] = y; mv[it] = m; nv[it] = rk*8 + ff;
        }
        if (more) { bar_arrive(barp); tgt += GCTAS; }   // B: inp published
        #pragma unroll
        for (int it = 0; it < 2; it++)                   // out stores hide in barB window
            out[(TSTEPS-1-t)*BATCH*IDIM + (row0+mv[it])*IDIM + nv[it]] = yv[it];

        if (more) {
            bar_wait(barp, tgt);         // B
            // ===== phase2: gates(t+1) inp-part; then publish gsm =====
            mma_chunks(acc, accfc, &g_act[pw][0][0], Ast, Wsm, row0, wr, wc, lrow, lseg,
                       HCHUNK, NCHUNK, false);
            #pragma unroll
            for (int i = 0; i < 2; i++)
                #pragma unroll
                for (int j = 0; j < 2; j++)
                    wmma::store_matrix_sync(&gsm[(wr*32 + i*16)*GPAD + wc*32 + j*16],
                                            acc[i][j], GPAD, wmma::mem_row_major);
            __syncthreads();
        }
    }
}

extern "C" void kernel_launch(void* const* d_in, const int* in_sizes, int n_in,
                              void* d_out, int out_size)
{
    const float* x    = (const float*)d_in[0];
    // d_in[1] = enc_hiddens : unused by the reference recursion
    const float* h0   = (const float*)d_in[2];
    const float* c0   = (const float*)d_in[3];
    const float* W_ih = (const float*)d_in[4];
    const float* W_hh = (const float*)d_in[5];
    const float* b_ih = (const float*)d_in[6];
    const float* b_hh = (const float*)d_in[7];
    const float* fc_W = (const float*)d_in[8];
    const float* fc_b = (const float*)d_in[9];
    float* out = (float*)d_out;

    cudaFuncSetAttribute(decoder_kernel, cudaFuncAttributeMaxDynamicSharedMemorySize, SMEM_BYTES);

    // Reset group-barrier counters every replay (captured memset node)
    void* barp = nullptr;
    cudaGetSymbolAddress(&barp, g_bar);
    cudaMemsetAsync(barp, 0, sizeof(unsigned) * NGROUPS);

    decoder_kernel<<<NCTA, NTHREADS, SMEM_BYTES>>>(x, h0, c0, W_ih, W_hh,
                                                   b_ih, b_hh, fc_W, fc_b, out);
}